// round 8
// baseline (speedup 1.0000x reference)
#include <cuda_runtime.h>
#include <cuda_fp16.h>
#include <cstdint>

#define N_NODES 100000
#define N_EDGES 800000
#define FEATS 128
#define NBS 196  // ceil(100000/512)

// Scratch (allocation-free rule: device globals)
__device__ __align__(16) float g_accum[(size_t)N_NODES * FEATS];   // mean rows (tf32 bits)
__device__ __align__(16) __half g_feat16[(size_t)N_NODES * FEATS]; // fp16 feat copy
__device__ __align__(16) unsigned g_Bf[32 * 16 * 32 * 2];  // tf32 frag-ordered B [256x128]
__device__ int g_cnt[N_NODES];
__device__ int g_row[N_NODES];
__device__ int g_cursor[N_NODES];
__device__ int g_esrc[N_EDGES];
__device__ int g_total;
__device__ int g_is64;

__device__ __forceinline__ unsigned to_tf32(float f) {
    unsigned r;
    asm("cvt.rna.tf32.f32 %0, %1;" : "=r"(r) : "f"(f));
    return r;
}

// ---------------------------------------------------------------------------
// k_prep: detect index width + zero counters/total + build frag-ordered tf32 B
// ---------------------------------------------------------------------------
__global__ void k_prep(const float* __restrict__ Wn, const float* __restrict__ Ws,
                       const int* __restrict__ src_raw) {
    int i = blockIdx.x * blockDim.x + threadIdx.x;
    if (i == 0) {
        int is64 = 1;
        for (int j = 0; j < 256; ++j)
            if (src_raw[2 * j + 1] != 0) { is64 = 0; break; }
        g_is64 = is64;
        g_total = 0;
    }
    if (i < N_NODES) g_cnt[i] = 0;
    if (i < 32 * 16 * 32) {
        int lane = i & 31;
        int nt = (i >> 5) & 15;
        int kc = i >> 9;
        int n = nt * 8 + (lane >> 2);
        int k0 = kc * 8 + (lane & 3);
        int k1 = k0 + 4;
        float v0 = (k0 < 128) ? Ws[n * 128 + k0] : Wn[n * 128 + (k0 - 128)];
        float v1 = (k1 < 128) ? Ws[n * 128 + k1] : Wn[n * 128 + (k1 - 128)];
        g_Bf[i * 2 + 0] = to_tf32(v0);
        g_Bf[i * 2 + 1] = to_tf32(v1);
    }
}

// ---------------------------------------------------------------------------
// k_count_conv: dst histogram (2 edges/thread for first 400k threads) fused
// with feat fp32->fp16 conversion (1.6M threads x 8 floats) — the conversion
// bandwidth hides the atomic latency.
// ---------------------------------------------------------------------------
__global__ __launch_bounds__(256) void k_count_conv(const void* __restrict__ dst_p,
                                                    const float* __restrict__ feat) {
    int t = blockIdx.x * blockDim.x + threadIdx.x;
    if (t < N_NODES * 16) {
        float4 a = ((const float4*)feat)[t * 2];
        float4 b = ((const float4*)feat)[t * 2 + 1];
        __half2 h[4];
        h[0] = __floats2half2_rn(a.x, a.y);
        h[1] = __floats2half2_rn(a.z, a.w);
        h[2] = __floats2half2_rn(b.x, b.y);
        h[3] = __floats2half2_rn(b.z, b.w);
        uint4 pack;
        pack.x = *(unsigned*)&h[0];
        pack.y = *(unsigned*)&h[1];
        pack.z = *(unsigned*)&h[2];
        pack.w = *(unsigned*)&h[3];
        ((uint4*)g_feat16)[t] = pack;
    }
    if (t < N_EDGES / 2) {
        int d0, d1;
        if (g_is64) {
            longlong2 v = ((const longlong2*)dst_p)[t];
            d0 = (int)v.x; d1 = (int)v.y;
        } else {
            int2 v = ((const int2*)dst_p)[t];
            d0 = v.x; d1 = v.y;
        }
        if ((unsigned)d0 < N_NODES) atomicAdd(&g_cnt[d0], 1);
        if ((unsigned)d1 < N_NODES) atomicAdd(&g_cnt[d1], 1);
    }
}

// ---------------------------------------------------------------------------
// k_scan: single-pass (block base via atomicAdd; buckets disjoint, order-free)
// ---------------------------------------------------------------------------
__global__ __launch_bounds__(512) void k_scan() {
    __shared__ int wsum[16];
    __shared__ int sbase;
    int i = blockIdx.x * 512 + threadIdx.x;
    int lane = threadIdx.x & 31, w = threadIdx.x >> 5;
    int v = (i < N_NODES) ? g_cnt[i] : 0;
    int incl = v;
#pragma unroll
    for (int o = 1; o < 32; o <<= 1) {
        int t = __shfl_up_sync(0xffffffffu, incl, o);
        if (lane >= o) incl += t;
    }
    if (lane == 31) wsum[w] = incl;
    __syncthreads();
    if (threadIdx.x < 16) {
        int x = wsum[threadIdx.x];
        int incl2 = x;
#pragma unroll
        for (int o = 1; o < 16; o <<= 1) {
            int t = __shfl_up_sync(0x0000ffffu, incl2, o);
            if ((int)threadIdx.x >= o) incl2 += t;
        }
        wsum[threadIdx.x] = incl2 - x;
        if (threadIdx.x == 15) sbase = atomicAdd(&g_total, incl2);
    }
    __syncthreads();
    if (i < N_NODES) {
        int r = sbase + (incl - v) + wsum[w];
        g_row[i] = r;
        g_cursor[i] = r;
    }
}

// ---------------------------------------------------------------------------
// k_reorder: 4 edges/thread (4 independent ATOMG chains for latency cover)
// ---------------------------------------------------------------------------
__global__ __launch_bounds__(256) void k_reorder(const void* __restrict__ src_p,
                                                 const void* __restrict__ dst_p) {
    int t = blockIdx.x * blockDim.x + threadIdx.x;
    if (t >= N_EDGES / 4) return;
    int s[4], d[4];
    if (g_is64) {
        const longlong2* sp = (const longlong2*)src_p;
        const longlong2* dp = (const longlong2*)dst_p;
        longlong2 vs0 = sp[t * 2], vs1 = sp[t * 2 + 1];
        longlong2 vd0 = dp[t * 2], vd1 = dp[t * 2 + 1];
        s[0] = (int)vs0.x; s[1] = (int)vs0.y; s[2] = (int)vs1.x; s[3] = (int)vs1.y;
        d[0] = (int)vd0.x; d[1] = (int)vd0.y; d[2] = (int)vd1.x; d[3] = (int)vd1.y;
    } else {
        int4 vs = ((const int4*)src_p)[t];
        int4 vd = ((const int4*)dst_p)[t];
        s[0] = vs.x; s[1] = vs.y; s[2] = vs.z; s[3] = vs.w;
        d[0] = vd.x; d[1] = vd.y; d[2] = vd.z; d[3] = vd.w;
    }
    int pos[4];
#pragma unroll
    for (int j = 0; j < 4; ++j)
        pos[j] = ((unsigned)d[j] < N_NODES && (unsigned)s[j] < N_NODES)
                     ? atomicAdd(&g_cursor[d[j]], 1)
                     : -1;
#pragma unroll
    for (int j = 0; j < 4; ++j)
        if (pos[j] >= 0) g_esrc[pos[j]] = s[j];
}

// ---------------------------------------------------------------------------
// k_gather: one warp per dst node; fp16 row reads (256B/row), fp32 accumulate,
// write tf32-bit mean (GEMM's cvt is idempotent on it).
// ---------------------------------------------------------------------------
__global__ __launch_bounds__(256) void k_gather() {
    int node = (blockIdx.x * blockDim.x + threadIdx.x) >> 5;
    int lane = threadIdx.x & 31;
    if (node >= N_NODES) return;
    int start = g_row[node];
    int deg = g_cnt[node];
    const int* es = g_esrc + start;

    float4 acc = make_float4(0.f, 0.f, 0.f, 0.f);
    int j = 0;
#define H4ACC(sid)                                                                 \
    {                                                                              \
        const __half2* hp = (const __half2*)(g_feat16 + (size_t)(sid)*FEATS + lane * 4); \
        __half2 h0 = hp[0], h1 = hp[1];                                            \
        float2 f0 = __half22float2(h0);                                            \
        float2 f1 = __half22float2(h1);                                            \
        acc.x += f0.x; acc.y += f0.y; acc.z += f1.x; acc.w += f1.y;                \
    }
    for (; j + 4 <= deg; j += 4) {
        int s0 = es[j], s1 = es[j + 1], s2 = es[j + 2], s3 = es[j + 3];
        H4ACC(s0); H4ACC(s1); H4ACC(s2); H4ACC(s3);
    }
    for (; j < deg; ++j) H4ACC(es[j]);
#undef H4ACC
    float inv = 1.0f / (float)max(deg, 1);
    float4 r;
    r.x = __uint_as_float(to_tf32(acc.x * inv));
    r.y = __uint_as_float(to_tf32(acc.y * inv));
    r.z = __uint_as_float(to_tf32(acc.z * inv));
    r.w = __uint_as_float(to_tf32(acc.w * inv));
    ((float4*)(g_accum + (size_t)node * FEATS))[lane] = r;
}

// ---------------------------------------------------------------------------
// Tensor-core GEMM (validated): out = [feat | mean] @ B + bias
// BM=128, BN=128, BK=32, 256 threads, tf32 mma.m16n8k8, smem B + A dbl-buffer.
// ---------------------------------------------------------------------------
#define A_STRIDE 132
#define A_BUF (32 * A_STRIDE)
#define BF_WORDS (32 * 16 * 32 * 2)
#define GEMM_SMEM ((BF_WORDS + 2 * A_BUF) * 4)

__global__ __launch_bounds__(256, 1) void k_gemm_tc(const float* __restrict__ feat,
                                                    const float* __restrict__ b_self,
                                                    float* __restrict__ out) {
    extern __shared__ unsigned smem_u[];
    unsigned* Bf = smem_u;
    unsigned* As = smem_u + BF_WORDS;

    int tid = threadIdx.x;
    int lane = tid & 31, wid = tid >> 5;
    int wm = wid & 1, wn = wid >> 1;
    int m0 = blockIdx.x * 128;

    {
        const uint4* src = (const uint4*)g_Bf;
        uint4* dstp = (uint4*)Bf;
#pragma unroll
        for (int i = 0; i < BF_WORDS / 4 / 256; ++i)
            dstp[tid + i * 256] = src[tid + i * 256];
    }

    float c[4][4][4];
#pragma unroll
    for (int a = 0; a < 4; a++)
#pragma unroll
        for (int b = 0; b < 4; b++)
#pragma unroll
            for (int r = 0; r < 4; r++) c[a][b][r] = 0.f;

    int mloc = tid >> 3;
    int kq = (tid & 7) * 4;
    float4 ra[4];
    const float4 z4 = make_float4(0.f, 0.f, 0.f, 0.f);

#define AGLOAD(kt)                                                              \
    {                                                                           \
        const float* A = ((kt) < 4) ? feat : g_accum;                           \
        int k0g = ((kt) & 3) * 32;                                              \
        _Pragma("unroll") for (int r = 0; r < 4; ++r) {                         \
            int m = m0 + mloc + 32 * r;                                         \
            ra[r] = (m < N_NODES)                                               \
                        ? *(const float4*)(A + (size_t)m * FEATS + k0g + kq)    \
                        : z4;                                                   \
        }                                                                       \
    }

#define ASTORE(buf)                                                             \
    {                                                                           \
        unsigned* Ab = As + (buf)*A_BUF;                                        \
        _Pragma("unroll") for (int r = 0; r < 4; ++r) {                         \
            int m = mloc + 32 * r;                                              \
            Ab[(kq + 0) * A_STRIDE + m] = to_tf32(ra[r].x);                     \
            Ab[(kq + 1) * A_STRIDE + m] = to_tf32(ra[r].y);                     \
            Ab[(kq + 2) * A_STRIDE + m] = to_tf32(ra[r].z);                     \
            Ab[(kq + 3) * A_STRIDE + m] = to_tf32(ra[r].w);                     \
        }                                                                       \
    }

    AGLOAD(0);
    ASTORE(0);
    __syncthreads();

    int r4 = lane >> 2, k4 = lane & 3;

    for (int kt = 0; kt < 8; ++kt) {
        int cur = kt & 1;
        if (kt < 7) AGLOAD(kt + 1);
        const unsigned* Ab = As + cur * A_BUF;
#pragma unroll
        for (int kk = 0; kk < 4; ++kk) {
            int k0 = kk * 8;
            int kc = kt * 4 + kk;
            unsigned bfrag[4][2];
#pragma unroll
            for (int nt = 0; nt < 4; ++nt) {
                const unsigned* p = Bf + ((kc * 16 + (wn * 4 + nt)) * 32 + lane) * 2;
                uint2 v = *(const uint2*)p;
                bfrag[nt][0] = v.x;
                bfrag[nt][1] = v.y;
            }
#pragma unroll
            for (int mt = 0; mt < 4; ++mt) {
                int mb = wm * 64 + mt * 16;
                unsigned a0 = Ab[(k0 + k4) * A_STRIDE + mb + r4];
                unsigned a1 = Ab[(k0 + k4) * A_STRIDE + mb + r4 + 8];
                unsigned a2 = Ab[(k0 + k4 + 4) * A_STRIDE + mb + r4];
                unsigned a3 = Ab[(k0 + k4 + 4) * A_STRIDE + mb + r4 + 8];
#pragma unroll
                for (int nt = 0; nt < 4; ++nt) {
                    asm("mma.sync.aligned.m16n8k8.row.col.f32.tf32.tf32.f32 "
                        "{%0,%1,%2,%3}, {%4,%5,%6,%7}, {%8,%9}, {%0,%1,%2,%3};"
                        : "+f"(c[mt][nt][0]), "+f"(c[mt][nt][1]),
                          "+f"(c[mt][nt][2]), "+f"(c[mt][nt][3])
                        : "r"(a0), "r"(a1), "r"(a2), "r"(a3),
                          "r"(bfrag[nt][0]), "r"(bfrag[nt][1]));
                }
            }
        }
        __syncthreads();
        if (kt < 7) {
            ASTORE(1 - cur);
            __syncthreads();
        }
    }

#pragma unroll
    for (int nt = 0; nt < 4; ++nt) {
        int col = wn * 32 + nt * 8 + (lane & 3) * 2;
        float b0 = b_self[col], b1 = b_self[col + 1];
#pragma unroll
        for (int mt = 0; mt < 4; ++mt) {
            int row = m0 + wm * 64 + mt * 16 + (lane >> 2);
            if (row < N_NODES) {
                float2 v0 = make_float2(c[mt][nt][0] + b0, c[mt][nt][1] + b1);
                *(float2*)(out + (size_t)row * FEATS + col) = v0;
            }
            if (row + 8 < N_NODES) {
                float2 v1 = make_float2(c[mt][nt][2] + b0, c[mt][nt][3] + b1);
                *(float2*)(out + (size_t)(row + 8) * FEATS + col) = v1;
            }
        }
    }
#undef AGLOAD
#undef ASTORE
}

// ---------------------------------------------------------------------------
extern "C" void kernel_launch(void* const* d_in, const int* in_sizes, int n_in,
                              void* d_out, int out_size) {
    const float* feat = (const float*)d_in[0];
    const void*  src  = d_in[1];
    const void*  dst  = d_in[2];
    const float* Wn   = (const float*)d_in[3];
    const float* Ws   = (const float*)d_in[4];
    const float* b    = (const float*)d_in[5];
    float*       out  = (float*)d_out;

    cudaFuncSetAttribute(k_gemm_tc, cudaFuncAttributeMaxDynamicSharedMemorySize,
                         GEMM_SMEM);

    k_prep<<<(N_NODES + 255) / 256, 256>>>(Wn, Ws, (const int*)src);
    k_count_conv<<<(N_NODES * 16 + 255) / 256, 256>>>(dst, feat);
    k_scan<<<NBS, 512>>>();
    k_reorder<<<(N_EDGES / 4 + 255) / 256, 256>>>(src, dst);
    k_gather<<<(N_NODES * 32 + 255) / 256, 256>>>();
    k_gemm_tc<<<(N_NODES + 127) / 128, 256, GEMM_SMEM>>>(feat, b, out);
}